// round 1
// baseline (speedup 1.0000x reference)
#include <cuda_runtime.h>

// Problem constants
#define N1_SRC 495616
#define N1_DST 45056
#define E1     450560
#define N2_SRC 45056
#define N2_DST 4096
#define E2     40960
#define D      512
#define DOUT   256

// ---------------- device scratch (static globals: allocation-free) ----------------
__device__ float g_agg1[(size_t)N1_DST * D];   // 92.3 MB
__device__ float g_h1  [(size_t)N1_DST * D];   // 92.3 MB
__device__ float g_agg2[(size_t)N2_DST * D];   // 8 MB

__device__ int g_cnt1[N1_DST];
__device__ int g_off1[N1_DST + 1];
__device__ int g_cur1[N1_DST];
__device__ int g_srt1[E1];

__device__ int g_cnt2[N2_DST];
__device__ int g_off2[N2_DST + 1];
__device__ int g_cur2[N2_DST];
__device__ int g_srt2[E2];

// ---------------- small utility kernels ----------------
__global__ void zero_i32_k(int* __restrict__ p, int n) {
    int i = blockIdx.x * blockDim.x + threadIdx.x;
    if (i < n) p[i] = 0;
}

__global__ void hist_k(const int* __restrict__ dst, int e, int* __restrict__ cnt) {
    int i = blockIdx.x * blockDim.x + threadIdx.x;
    if (i < e) atomicAdd(&cnt[dst[i]], 1);
}

// single-block exclusive scan (n up to ~64K), also copies result into cursor array
__global__ void scan_k(const int* __restrict__ cnt, int* __restrict__ off,
                       int* __restrict__ cur, int n) {
    __shared__ int buf[1024];
    __shared__ int carry;
    int tid = threadIdx.x;
    if (tid == 0) carry = 0;
    __syncthreads();
    for (int base = 0; base < n; base += 1024) {
        int i = base + tid;
        int v = (i < n) ? cnt[i] : 0;
        buf[tid] = v;
        __syncthreads();
        // Hillis-Steele inclusive scan
        for (int s = 1; s < 1024; s <<= 1) {
            int t = (tid >= s) ? buf[tid - s] : 0;
            __syncthreads();
            buf[tid] += t;
            __syncthreads();
        }
        int excl = carry + buf[tid] - v;
        if (i < n) { off[i] = excl; cur[i] = excl; }
        __syncthreads();
        if (tid == 0) carry += buf[1023];
        __syncthreads();
    }
    if (tid == 0) off[n] = carry;
}

__global__ void scatter_k(const int* __restrict__ src, const int* __restrict__ dst,
                          int e, int* __restrict__ cur, int* __restrict__ srt) {
    int i = blockIdx.x * blockDim.x + threadIdx.x;
    if (i < e) {
        int d = dst[i];
        int p = atomicAdd(&cur[d], 1);
        srt[p] = src[i];
    }
}

// ---------------- aggregation: one CTA (128 threads) per destination node ----------------
// out[node] = (feat[node] + sum_{s in neighbors(node)} feat[s]) / (deg + 1)
__global__ void __launch_bounds__(128)
agg_k(const float* __restrict__ feat, const int* __restrict__ off,
      const int* __restrict__ srt, float* __restrict__ out) {
    int node = blockIdx.x;
    int t = threadIdx.x;                  // covers 4 floats: cols t*4 .. t*4+3
    const float4* fp = (const float4*)feat;
    int b = off[node], e = off[node + 1];

    float4 acc = fp[(size_t)node * (D / 4) + t];   // self term (h_dst)
    int j = b;
    for (; j + 1 < e; j += 2) {
        int s0 = srt[j], s1 = srt[j + 1];
        float4 v0 = fp[(size_t)s0 * (D / 4) + t];
        float4 v1 = fp[(size_t)s1 * (D / 4) + t];
        acc.x += v0.x; acc.y += v0.y; acc.z += v0.z; acc.w += v0.w;
        acc.x += v1.x; acc.y += v1.y; acc.z += v1.z; acc.w += v1.w;
    }
    if (j < e) {
        int s0 = srt[j];
        float4 v0 = fp[(size_t)s0 * (D / 4) + t];
        acc.x += v0.x; acc.y += v0.y; acc.z += v0.z; acc.w += v0.w;
    }
    float sc = 1.0f / (float)(e - b + 1);
    acc.x *= sc; acc.y *= sc; acc.z *= sc; acc.w *= sc;
    ((float4*)out)[(size_t)node * (D / 4) + t] = acc;
}

// ---------------- SIMT fp32 GEMM: C[M,N] = A[M,K] * B[K,N] + bias (opt relu) ----------------
// BM=128, BN=128, BK=16, 256 threads, 8x8 microtile, register-prefetch pipeline.
// All dims assumed multiples of tile sizes (true for this problem).
__global__ void __launch_bounds__(256)
sgemm_k(const float* __restrict__ A, const float* __restrict__ B,
        const float* __restrict__ bias, float* __restrict__ C,
        int K, int lda, int ldb, int ldc, int relu) {
    __shared__ float As[16][132];   // [BK][BM+4] transposed, padded
    __shared__ float Bs[16][128];   // [BK][BN]

    int tid = threadIdx.x;
    int tx = tid & 15;              // 0..15 -> N microtile
    int ty = tid >> 4;              // 0..15 -> M microtile
    int m0 = blockIdx.y * 128;
    int n0 = blockIdx.x * 128;

    const float* Ag = A + (size_t)m0 * lda;
    const float* Bg = B + n0;

    int arow = tid >> 2;            // 0..63
    int acol = (tid & 3) << 2;      // 0,4,8,12
    int brow = tid >> 5;            // 0..7
    int bcol = (tid & 31) << 2;     // 0..124

    // prefetch k-tile 0 into registers
    float4 pa0 = *(const float4*)&Ag[(size_t)arow        * lda + acol];
    float4 pa1 = *(const float4*)&Ag[(size_t)(arow + 64) * lda + acol];
    float4 pb0 = *(const float4*)&Bg[(size_t)brow        * ldb + bcol];
    float4 pb1 = *(const float4*)&Bg[(size_t)(brow + 8)  * ldb + bcol];

    float acc[8][8];
#pragma unroll
    for (int i = 0; i < 8; i++)
#pragma unroll
        for (int j = 0; j < 8; j++) acc[i][j] = 0.0f;

    int ktiles = K / 16;
    for (int t = 0; t < ktiles; t++) {
        // commit prefetched tile to smem (A transposed)
        As[acol + 0][arow] = pa0.x; As[acol + 1][arow] = pa0.y;
        As[acol + 2][arow] = pa0.z; As[acol + 3][arow] = pa0.w;
        As[acol + 0][arow + 64] = pa1.x; As[acol + 1][arow + 64] = pa1.y;
        As[acol + 2][arow + 64] = pa1.z; As[acol + 3][arow + 64] = pa1.w;
        *(float4*)&Bs[brow][bcol]     = pb0;
        *(float4*)&Bs[brow + 8][bcol] = pb1;
        __syncthreads();

        // prefetch next k-tile (overlaps with compute below)
        if (t + 1 < ktiles) {
            int k0 = (t + 1) * 16;
            pa0 = *(const float4*)&Ag[(size_t)arow        * lda + k0 + acol];
            pa1 = *(const float4*)&Ag[(size_t)(arow + 64) * lda + k0 + acol];
            pb0 = *(const float4*)&Bg[(size_t)(k0 + brow)     * ldb + bcol];
            pb1 = *(const float4*)&Bg[(size_t)(k0 + brow + 8) * ldb + bcol];
        }

#pragma unroll
        for (int kk = 0; kk < 16; kk++) {
            float a[8], bq[8];
            *(float4*)&a[0]  = *(const float4*)&As[kk][ty * 8];
            *(float4*)&a[4]  = *(const float4*)&As[kk][ty * 8 + 4];
            *(float4*)&bq[0] = *(const float4*)&Bs[kk][tx * 8];
            *(float4*)&bq[4] = *(const float4*)&Bs[kk][tx * 8 + 4];
#pragma unroll
            for (int i = 0; i < 8; i++)
#pragma unroll
                for (int j = 0; j < 8; j++)
                    acc[i][j] = fmaf(a[i], bq[j], acc[i][j]);
        }
        __syncthreads();
    }

    // epilogue: bias (+ optional relu), vectorized store
    float bb[8];
#pragma unroll
    for (int j = 0; j < 8; j++) bb[j] = bias[n0 + tx * 8 + j];

#pragma unroll
    for (int i = 0; i < 8; i++) {
        int row = m0 + ty * 8 + i;
        float4 o0, o1;
        o0.x = acc[i][0] + bb[0]; o0.y = acc[i][1] + bb[1];
        o0.z = acc[i][2] + bb[2]; o0.w = acc[i][3] + bb[3];
        o1.x = acc[i][4] + bb[4]; o1.y = acc[i][5] + bb[5];
        o1.z = acc[i][6] + bb[6]; o1.w = acc[i][7] + bb[7];
        if (relu) {
            o0.x = fmaxf(o0.x, 0.f); o0.y = fmaxf(o0.y, 0.f);
            o0.z = fmaxf(o0.z, 0.f); o0.w = fmaxf(o0.w, 0.f);
            o1.x = fmaxf(o1.x, 0.f); o1.y = fmaxf(o1.y, 0.f);
            o1.z = fmaxf(o1.z, 0.f); o1.w = fmaxf(o1.w, 0.f);
        }
        *(float4*)&C[(size_t)row * ldc + n0 + tx * 8]     = o0;
        *(float4*)&C[(size_t)row * ldc + n0 + tx * 8 + 4] = o1;
    }
}

// ---------------- launch ----------------
extern "C" void kernel_launch(void* const* d_in, const int* in_sizes, int n_in,
                              void* d_out, int out_size) {
    const float* feats = (const float*)d_in[0];
    const float* W1    = (const float*)d_in[1];
    const float* b1    = (const float*)d_in[2];
    const float* W2    = (const float*)d_in[3];
    const float* b2    = (const float*)d_in[4];
    const int*   es1   = (const int*)d_in[5];
    const int*   ed1   = (const int*)d_in[6];
    const int*   es2   = (const int*)d_in[7];
    const int*   ed2   = (const int*)d_in[8];
    float* out = (float*)d_out;

    float *agg1, *h1, *agg2;
    int *cnt1, *off1, *cur1, *srt1;
    int *cnt2, *off2, *cur2, *srt2;
    cudaGetSymbolAddress((void**)&agg1, g_agg1);
    cudaGetSymbolAddress((void**)&h1,   g_h1);
    cudaGetSymbolAddress((void**)&agg2, g_agg2);
    cudaGetSymbolAddress((void**)&cnt1, g_cnt1);
    cudaGetSymbolAddress((void**)&off1, g_off1);
    cudaGetSymbolAddress((void**)&cur1, g_cur1);
    cudaGetSymbolAddress((void**)&srt1, g_srt1);
    cudaGetSymbolAddress((void**)&cnt2, g_cnt2);
    cudaGetSymbolAddress((void**)&off2, g_off2);
    cudaGetSymbolAddress((void**)&cur2, g_cur2);
    cudaGetSymbolAddress((void**)&srt2, g_srt2);

    // ---- CSR build (both layers) ----
    zero_i32_k<<<(N1_DST + 255) / 256, 256>>>(cnt1, N1_DST);
    zero_i32_k<<<(N2_DST + 255) / 256, 256>>>(cnt2, N2_DST);
    hist_k<<<(E1 + 255) / 256, 256>>>(ed1, E1, cnt1);
    hist_k<<<(E2 + 255) / 256, 256>>>(ed2, E2, cnt2);
    scan_k<<<1, 1024>>>(cnt1, off1, cur1, N1_DST);
    scan_k<<<1, 1024>>>(cnt2, off2, cur2, N2_DST);
    scatter_k<<<(E1 + 255) / 256, 256>>>(es1, ed1, E1, cur1, srt1);
    scatter_k<<<(E2 + 255) / 256, 256>>>(es2, ed2, E2, cur2, srt2);

    // ---- layer 1: aggregate -> GEMM(+bias,relu) ----
    agg_k<<<N1_DST, 128>>>(feats, off1, srt1, agg1);
    {
        dim3 grid(D / 128, N1_DST / 128);   // (4, 352)
        sgemm_k<<<grid, 256>>>(agg1, W1, b1, h1, D, D, D, D, 1);
    }

    // ---- layer 2: aggregate -> GEMM(+bias) -> out ----
    agg_k<<<N2_DST, 128>>>(h1, off2, srt2, agg2);
    {
        dim3 grid(DOUT / 128, N2_DST / 128);  // (2, 32)
        sgemm_k<<<grid, 256>>>(agg2, W2, b2, out, D, D, DOUT, DOUT, 0);
    }
}

// round 3
// speedup vs baseline: 2.4530x; 2.4530x over previous
#include <cuda_runtime.h>
#include <cuda_bf16.h>
#include <cstdint>

// Problem constants
#define N1_SRC 495616
#define N1_DST 45056
#define E1     450560
#define N2_SRC 45056
#define N2_DST 4096
#define E2     40960
#define D      512
#define DOUT   256

// ---------------- device scratch ----------------
__device__ float g_h1[(size_t)N1_DST * D];                   // layer-1 output (fp32)
__device__ __nv_bfloat16 g_a1hi[(size_t)N1_DST * D];
__device__ __nv_bfloat16 g_a1lo[(size_t)N1_DST * D];
__device__ __nv_bfloat16 g_a2hi[(size_t)N2_DST * D];
__device__ __nv_bfloat16 g_a2lo[(size_t)N2_DST * D];
__device__ __nv_bfloat16 g_w1hi[(size_t)D * D];              // W1^T [N=512,K=512]
__device__ __nv_bfloat16 g_w1lo[(size_t)D * D];
__device__ __nv_bfloat16 g_w2hi[(size_t)DOUT * D];           // W2^T [N=256,K=512]
__device__ __nv_bfloat16 g_w2lo[(size_t)DOUT * D];

__device__ int g_cnt1[N1_DST];
__device__ int g_off1[N1_DST + 1];
__device__ int g_cur1[N1_DST];
__device__ int g_srt1[E1];
__device__ int g_cnt2[N2_DST];
__device__ int g_off2[N2_DST + 1];
__device__ int g_cur2[N2_DST];
__device__ int g_srt2[E2];

// ---------------- PTX helpers (base-target safe: no tcgen05) ----------------
__device__ __forceinline__ uint32_t smem_u32(const void* p) {
    uint32_t a;
    asm("{ .reg .u64 t; cvta.to.shared.u64 t, %1; cvt.u32.u64 %0, t; }" : "=r"(a) : "l"(p));
    return a;
}

__device__ __forceinline__ void cp16(uint32_t s, const void* g) {
    asm volatile("cp.async.cg.shared.global [%0], [%1], 16;" :: "r"(s), "l"(g));
}
__device__ __forceinline__ void cp_commit() {
    asm volatile("cp.async.commit_group;" ::: "memory");
}
template <int N>
__device__ __forceinline__ void cp_wait() {
    asm volatile("cp.async.wait_group %0;" :: "n"(N) : "memory");
}

__device__ __forceinline__ void ldm_x4(uint32_t* r, uint32_t addr) {
    asm volatile("ldmatrix.sync.aligned.m8n8.x4.shared.b16 {%0,%1,%2,%3}, [%4];"
                 : "=r"(r[0]), "=r"(r[1]), "=r"(r[2]), "=r"(r[3]) : "r"(addr));
}

// D = A(bf16) * B(bf16) + D, m16n8k16, fp32 accum
__device__ __forceinline__ void mma_bf16(float* c, const uint32_t* a, const uint32_t* b) {
    asm volatile(
        "mma.sync.aligned.m16n8k16.row.col.f32.bf16.bf16.f32 "
        "{%0,%1,%2,%3}, {%4,%5,%6,%7}, {%8,%9}, {%0,%1,%2,%3};"
        : "+f"(c[0]), "+f"(c[1]), "+f"(c[2]), "+f"(c[3])
        : "r"(a[0]), "r"(a[1]), "r"(a[2]), "r"(a[3]), "r"(b[0]), "r"(b[1]));
}

// ---------------- small utility kernels ----------------
__global__ void zero_i32_k(int* __restrict__ p, int n) {
    int i = blockIdx.x * blockDim.x + threadIdx.x;
    if (i < n) p[i] = 0;
}

__global__ void hist_k(const int* __restrict__ dst, int e, int* __restrict__ cnt) {
    int i = blockIdx.x * blockDim.x + threadIdx.x;
    if (i < e) atomicAdd(&cnt[dst[i]], 1);
}

// single-block shfl-based exclusive scan
__global__ void scan_k(const int* __restrict__ cnt, int* __restrict__ off,
                       int* __restrict__ cur, int n) {
    __shared__ int wsum[32];
    __shared__ int carry_s;
    int tid = threadIdx.x, lane = tid & 31, w = tid >> 5;
    if (tid == 0) carry_s = 0;
    __syncthreads();
    for (int base = 0; base < n; base += 1024) {
        int i = base + tid;
        int v = (i < n) ? cnt[i] : 0;
        int x = v;
#pragma unroll
        for (int s = 1; s < 32; s <<= 1) {
            int t = __shfl_up_sync(0xFFFFFFFFu, x, s);
            if (lane >= s) x += t;
        }
        if (lane == 31) wsum[w] = x;
        __syncthreads();
        if (w == 0) {
            int y = wsum[lane];
#pragma unroll
            for (int s = 1; s < 32; s <<= 1) {
                int t = __shfl_up_sync(0xFFFFFFFFu, y, s);
                if (lane >= s) y += t;
            }
            wsum[lane] = y;
        }
        __syncthreads();
        int warp_excl = (w == 0) ? 0 : wsum[w - 1];
        int incl = carry_s + warp_excl + x;
        if (i < n) { off[i] = incl - v; cur[i] = incl - v; }
        __syncthreads();
        if (tid == 1023) carry_s = incl;
        __syncthreads();
    }
    if (threadIdx.x == 0) off[n] = carry_s;
}

__global__ void scatter_k(const int* __restrict__ src, const int* __restrict__ dst,
                          int e, int* __restrict__ cur, int* __restrict__ srt) {
    int i = blockIdx.x * blockDim.x + threadIdx.x;
    if (i < e) {
        int d = dst[i];
        int p = atomicAdd(&cur[d], 1);
        srt[p] = src[i];
    }
}

// W [K,N] fp32 -> Wt_hi/lo [N,K] bf16 split
__global__ void wsplit_k(const float* __restrict__ W, int K, int N,
                         __nv_bfloat16* __restrict__ thi, __nv_bfloat16* __restrict__ tlo) {
    int i = blockIdx.x * blockDim.x + threadIdx.x;
    if (i >= N * K) return;
    int n = i / K, k = i - n * K;
    float v = W[(size_t)k * N + n];
    __nv_bfloat16 h = __float2bfloat16_rn(v);
    float r = v - __bfloat162float(h);
    thi[i] = h;
    tlo[i] = __float2bfloat16_rn(r);
}

// ---------------- aggregation: one CTA (128 threads) per dst node, bf16 split out ----------------
__global__ void __launch_bounds__(128)
agg_split_k(const float* __restrict__ feat, const int* __restrict__ off,
            const int* __restrict__ srt,
            __nv_bfloat16* __restrict__ ahi, __nv_bfloat16* __restrict__ alo) {
    int node = blockIdx.x;
    int t = threadIdx.x;                  // covers cols t*4 .. t*4+3
    const float4* fp = (const float4*)feat;
    int b = off[node], e = off[node + 1];

    float4 acc = fp[(size_t)node * (D / 4) + t];
    int j = b;
    for (; j + 1 < e; j += 2) {
        int s0 = srt[j], s1 = srt[j + 1];
        float4 v0 = fp[(size_t)s0 * (D / 4) + t];
        float4 v1 = fp[(size_t)s1 * (D / 4) + t];
        acc.x += v0.x; acc.y += v0.y; acc.z += v0.z; acc.w += v0.w;
        acc.x += v1.x; acc.y += v1.y; acc.z += v1.z; acc.w += v1.w;
    }
    if (j < e) {
        int s0 = srt[j];
        float4 v0 = fp[(size_t)s0 * (D / 4) + t];
        acc.x += v0.x; acc.y += v0.y; acc.z += v0.z; acc.w += v0.w;
    }
    float sc = 1.0f / (float)(e - b + 1);
    float v[4] = { acc.x * sc, acc.y * sc, acc.z * sc, acc.w * sc };

    ushort4 hi, lo;
    __nv_bfloat16 h;
    h = __float2bfloat16_rn(v[0]); hi.x = __bfloat16_as_ushort(h);
    lo.x = __bfloat16_as_ushort(__float2bfloat16_rn(v[0] - __bfloat162float(h)));
    h = __float2bfloat16_rn(v[1]); hi.y = __bfloat16_as_ushort(h);
    lo.y = __bfloat16_as_ushort(__float2bfloat16_rn(v[1] - __bfloat162float(h)));
    h = __float2bfloat16_rn(v[2]); hi.z = __bfloat16_as_ushort(h);
    lo.z = __bfloat16_as_ushort(__float2bfloat16_rn(v[2] - __bfloat162float(h)));
    h = __float2bfloat16_rn(v[3]); hi.w = __bfloat16_as_ushort(h);
    lo.w = __bfloat16_as_ushort(__float2bfloat16_rn(v[3] - __bfloat162float(h)));

    ((ushort4*)ahi)[(size_t)node * (D / 4) + t] = hi;
    ((ushort4*)alo)[(size_t)node * (D / 4) + t] = lo;
}

// ---------------- HMMA split-bf16 GEMM ----------------
// C[M,N] = (Ahi+Alo)[M,K] @ (Bhi+Blo)^T + bias (opt relu)
// A: [M,K] bf16 row-major (hi/lo). B: [N,K] bf16 row-major (hi/lo).
// Tile 128x128, BK=32, 8 warps (4M x 2N), warp tile 32x64.
// cp.async double-buffered smem, 80B padded rows (conflict-free ldmatrix).
#define BK 32
#define ROWB 80                           // 32 bf16 = 64B + 16B pad
#define MAT_BYTES (128 * ROWB)            // 10240
#define STAGE_BYTES (4 * MAT_BYTES)       // 40960
#define GEMM_SMEM (2 * STAGE_BYTES)       // 81920

__device__ __forceinline__ void issue_chunk(
    uint32_t sstage, const char* gA_hi, const char* gA_lo,
    const char* gB_hi, const char* gB_lo, int kc, int tid) {
    const char* gp[4] = { gA_hi, gA_lo, gB_hi, gB_lo };
#pragma unroll
    for (int j = 0; j < 8; j++) {
        int i = tid + j * 256;            // 0..2047
        int mat = i >> 9;                 // 0..3
        int r = (i >> 2) & 127;           // row 0..127
        int c16 = i & 3;                  // 16B column
        const char* g = gp[mat] + (size_t)r * (D * 2) + kc * 64 + c16 * 16;
        cp16(sstage + mat * MAT_BYTES + r * ROWB + c16 * 16, g);
    }
    cp_commit();
}

__global__ void __launch_bounds__(256, 1)
gemm_hmma_k(const __nv_bfloat16* __restrict__ Ahi, const __nv_bfloat16* __restrict__ Alo,
            const __nv_bfloat16* __restrict__ Bhi, const __nv_bfloat16* __restrict__ Blo,
            const float* __restrict__ bias, float* __restrict__ C,
            int ldc, int relu) {
    extern __shared__ char smem[];
    uint32_t sm = smem_u32(smem);
    int tid = threadIdx.x;
    int wid = tid >> 5, lane = tid & 31;
    int wm = wid & 3;                     // 0..3 (M)
    int wn = wid >> 2;                    // 0..1 (N)
    int m0 = blockIdx.y * 128;
    int n0 = blockIdx.x * 128;

    const char* gAh = (const char*)(Ahi + (size_t)m0 * D);
    const char* gAl = (const char*)(Alo + (size_t)m0 * D);
    const char* gBh = (const char*)(Bhi + (size_t)n0 * D);
    const char* gBl = (const char*)(Blo + (size_t)n0 * D);

    float acc[2][8][4];
#pragma unroll
    for (int mt = 0; mt < 2; mt++)
#pragma unroll
        for (int nt = 0; nt < 8; nt++)
#pragma unroll
            for (int r = 0; r < 4; r++) acc[mt][nt][r] = 0.0f;

    const int NCH = D / BK;               // 16
    issue_chunk(sm, gAh, gAl, gBh, gBl, 0, tid);

    // ldmatrix lane addressing (constant across chunks, varies by kk)
    // A: row = wm*32 + mt*16 + (lane&15), kbyte = kk*32 + (lane>>4)*16
    // B: n = wn*64 + ng*16 + ((lane>>4)&1)*8 + (lane&7), kbyte = kk*32 + ((lane>>3)&1)*16
    int a_row = wm * 32 + (lane & 15);
    int a_kb = (lane >> 4) * 16;
    int b_row = wn * 64 + ((lane >> 4) & 1) * 8 + (lane & 7);
    int b_kb = ((lane >> 3) & 1) * 16;

    for (int c = 0; c < NCH; c++) {
        uint32_t st = sm + (c & 1) * STAGE_BYTES;
        if (c + 1 < NCH) {
            issue_chunk(sm + ((c + 1) & 1) * STAGE_BYTES, gAh, gAl, gBh, gBl, c + 1, tid);
            cp_wait<1>();
        } else {
            cp_wait<0>();
        }
        __syncthreads();

        uint32_t sAh = st;
        uint32_t sAl = st + MAT_BYTES;
        uint32_t sBh = st + 2 * MAT_BYTES;
        uint32_t sBl = st + 3 * MAT_BYTES;

#pragma unroll
        for (int kk = 0; kk < 2; kk++) {
            uint32_t ah[2][4], al[2][4];
#pragma unroll
            for (int mt = 0; mt < 2; mt++) {
                uint32_t ao = (a_row + mt * 16) * ROWB + kk * 32 + a_kb;
                ldm_x4(ah[mt], sAh + ao);
                ldm_x4(al[mt], sAl + ao);
            }
#pragma unroll
            for (int ng = 0; ng < 4; ng++) {
                uint32_t bh[4], bl[4];
                uint32_t bo = (b_row + ng * 16) * ROWB + kk * 32 + b_kb;
                ldm_x4(bh, sBh + bo);
                ldm_x4(bl, sBl + bo);
#pragma unroll
                for (int mt = 0; mt < 2; mt++) {
#pragma unroll
                    for (int hf = 0; hf < 2; hf++) {
                        int nt = ng * 2 + hf;
                        mma_bf16(acc[mt][nt], ah[mt], &bh[hf * 2]);
                        mma_bf16(acc[mt][nt], ah[mt], &bl[hf * 2]);
                        mma_bf16(acc[mt][nt], al[mt], &bh[hf * 2]);
                    }
                }
            }
        }
        __syncthreads();
    }

    // epilogue: direct global stores (32B-sector aligned float2 per thread)
#pragma unroll
    for (int mt = 0; mt < 2; mt++) {
        int row0 = m0 + wm * 32 + mt * 16 + (lane >> 2);
#pragma unroll
        for (int nt = 0; nt < 8; nt++) {
            int col = n0 + wn * 64 + nt * 8 + (lane & 3) * 2;
            float b0 = bias[col], b1 = bias[col + 1];
            float2 v0, v1;
            v0.x = acc[mt][nt][0] + b0; v0.y = acc[mt][nt][1] + b1;
            v1.x = acc[mt][nt][2] + b0; v1.y = acc[mt][nt][3] + b1;
            if (relu) {
                v0.x = fmaxf(v0.x, 0.f); v0.y = fmaxf(v0.y, 0.f);
                v1.x = fmaxf(v1.x, 0.f); v1.y = fmaxf(v1.y, 0.f);
            }
            *(float2*)&C[(size_t)row0 * ldc + col] = v0;
            *(float2*)&C[(size_t)(row0 + 8) * ldc + col] = v1;
        }
    }
}

// ---------------- launch ----------------
extern "C" void kernel_launch(void* const* d_in, const int* in_sizes, int n_in,
                              void* d_out, int out_size) {
    const float* feats = (const float*)d_in[0];
    const float* W1    = (const float*)d_in[1];
    const float* b1    = (const float*)d_in[2];
    const float* W2    = (const float*)d_in[3];
    const float* b2    = (const float*)d_in[4];
    const int*   es1   = (const int*)d_in[5];
    const int*   ed1   = (const int*)d_in[6];
    const int*   es2   = (const int*)d_in[7];
    const int*   ed2   = (const int*)d_in[8];
    float* out = (float*)d_out;

    float* h1;
    __nv_bfloat16 *a1hi, *a1lo, *a2hi, *a2lo, *w1hi, *w1lo, *w2hi, *w2lo;
    int *cnt1, *off1, *cur1, *srt1, *cnt2, *off2, *cur2, *srt2;
    cudaGetSymbolAddress((void**)&h1,   g_h1);
    cudaGetSymbolAddress((void**)&a1hi, g_a1hi);
    cudaGetSymbolAddress((void**)&a1lo, g_a1lo);
    cudaGetSymbolAddress((void**)&a2hi, g_a2hi);
    cudaGetSymbolAddress((void**)&a2lo, g_a2lo);
    cudaGetSymbolAddress((void**)&w1hi, g_w1hi);
    cudaGetSymbolAddress((void**)&w1lo, g_w1lo);
    cudaGetSymbolAddress((void**)&w2hi, g_w2hi);
    cudaGetSymbolAddress((void**)&w2lo, g_w2lo);
    cudaGetSymbolAddress((void**)&cnt1, g_cnt1);
    cudaGetSymbolAddress((void**)&off1, g_off1);
    cudaGetSymbolAddress((void**)&cur1, g_cur1);
    cudaGetSymbolAddress((void**)&srt1, g_srt1);
    cudaGetSymbolAddress((void**)&cnt2, g_cnt2);
    cudaGetSymbolAddress((void**)&off2, g_off2);
    cudaGetSymbolAddress((void**)&cur2, g_cur2);
    cudaGetSymbolAddress((void**)&srt2, g_srt2);

    cudaFuncSetAttribute(gemm_hmma_k, cudaFuncAttributeMaxDynamicSharedMemorySize, GEMM_SMEM);

    // ---- CSR build + weight prep ----
    zero_i32_k<<<(N1_DST + 255) / 256, 256>>>(cnt1, N1_DST);
    zero_i32_k<<<(N2_DST + 255) / 256, 256>>>(cnt2, N2_DST);
    hist_k<<<(E1 + 255) / 256, 256>>>(ed1, E1, cnt1);
    hist_k<<<(E2 + 255) / 256, 256>>>(ed2, E2, cnt2);
    scan_k<<<1, 1024>>>(cnt1, off1, cur1, N1_DST);
    scan_k<<<1, 1024>>>(cnt2, off2, cur2, N2_DST);
    scatter_k<<<(E1 + 255) / 256, 256>>>(es1, ed1, E1, cur1, srt1);
    scatter_k<<<(E2 + 255) / 256, 256>>>(es2, ed2, E2, cur2, srt2);
    wsplit_k<<<(D * D + 255) / 256, 256>>>(W1, D, D, w1hi, w1lo);
    wsplit_k<<<(DOUT * D + 255) / 256, 256>>>(W2, D, DOUT, w2hi, w2lo);

    // ---- layer 1 ----
    agg_split_k<<<N1_DST, 128>>>(feats, off1, srt1, a1hi, a1lo);
    {
        dim3 grid(D / 128, N1_DST / 128);   // (4, 352)
        gemm_hmma_k<<<grid, 256, GEMM_SMEM>>>(a1hi, a1lo, w1hi, w1lo, b1, h1, D, 1);
    }

    // ---- layer 2 ----
    agg_split_k<<<N2_DST, 128>>>(h1, off2, srt2, a2hi, a2lo);
    {
        dim3 grid(DOUT / 128, N2_DST / 128);  // (2, 32)
        gemm_hmma_k<<<grid, 256, GEMM_SMEM>>>(a2hi, a2lo, w2hi, w2lo, b2, out, DOUT, 0);
    }
}

// round 4
// speedup vs baseline: 2.7715x; 1.1298x over previous
#include <cuda_runtime.h>
#include <cuda_bf16.h>
#include <cstdint>

// Problem constants
#define N1_SRC 495616
#define N1_DST 45056
#define E1     450560
#define N2_SRC 45056
#define N2_DST 4096
#define E2     40960
#define D      512
#define DOUT   256

// ---------------- device scratch ----------------
__device__ float g_h1[(size_t)N1_DST * D];                   // layer-1 output (fp32)
__device__ __nv_bfloat16 g_a1hi[(size_t)N1_DST * D];
__device__ __nv_bfloat16 g_a1lo[(size_t)N1_DST * D];
__device__ __nv_bfloat16 g_a2hi[(size_t)N2_DST * D];
__device__ __nv_bfloat16 g_a2lo[(size_t)N2_DST * D];
__device__ __nv_bfloat16 g_w1hi[(size_t)D * D];              // W1^T [N=512,K=512]
__device__ __nv_bfloat16 g_w1lo[(size_t)D * D];
__device__ __nv_bfloat16 g_w2hi[(size_t)DOUT * D];           // W2^T [N=256,K=512]
__device__ __nv_bfloat16 g_w2lo[(size_t)DOUT * D];

__device__ int g_cnt1[N1_DST];
__device__ int g_off1[N1_DST + 1];
__device__ int g_cur1[N1_DST];
__device__ int g_srt1[E1];
__device__ int g_cnt2[N2_DST];
__device__ int g_off2[N2_DST + 1];
__device__ int g_cur2[N2_DST];
__device__ int g_srt2[E2];

// ---------------- PTX helpers (base-target safe: no tcgen05) ----------------
__device__ __forceinline__ uint32_t smem_u32(const void* p) {
    uint32_t a;
    asm("{ .reg .u64 t; cvta.to.shared.u64 t, %1; cvt.u32.u64 %0, t; }" : "=r"(a) : "l"(p));
    return a;
}

__device__ __forceinline__ void cp16(uint32_t s, const void* g) {
    asm volatile("cp.async.cg.shared.global [%0], [%1], 16;" :: "r"(s), "l"(g));
}
__device__ __forceinline__ void cp_commit() {
    asm volatile("cp.async.commit_group;" ::: "memory");
}
template <int N>
__device__ __forceinline__ void cp_wait() {
    asm volatile("cp.async.wait_group %0;" :: "n"(N) : "memory");
}

__device__ __forceinline__ void ldm_x4(uint32_t* r, uint32_t addr) {
    asm volatile("ldmatrix.sync.aligned.m8n8.x4.shared.b16 {%0,%1,%2,%3}, [%4];"
                 : "=r"(r[0]), "=r"(r[1]), "=r"(r[2]), "=r"(r[3]) : "r"(addr));
}

// D = A(bf16) * B(bf16) + D, m16n8k16, fp32 accum
__device__ __forceinline__ void mma_bf16(float* c, const uint32_t* a, const uint32_t* b) {
    asm volatile(
        "mma.sync.aligned.m16n8k16.row.col.f32.bf16.bf16.f32 "
        "{%0,%1,%2,%3}, {%4,%5,%6,%7}, {%8,%9}, {%0,%1,%2,%3};"
        : "+f"(c[0]), "+f"(c[1]), "+f"(c[2]), "+f"(c[3])
        : "r"(a[0]), "r"(a[1]), "r"(a[2]), "r"(a[3]), "r"(b[0]), "r"(b[1]));
}

// ---------------- fused CSR/prep kernels (both layers in one launch each) ----------------
__global__ void hist_all_k(const int* __restrict__ ed1, const int* __restrict__ ed2,
                           int* __restrict__ cnt1, int* __restrict__ cnt2) {
    int i = blockIdx.x * blockDim.x + threadIdx.x;
    if (i < E1) atomicAdd(&cnt1[ed1[i]], 1);
    else if (i < E1 + E2) atomicAdd(&cnt2[ed2[i - E1]], 1);
}

// per-block exclusive scan; block 0 -> layer1, block 1 -> layer2
__global__ void scan_all_k(const int* __restrict__ cnt1, int* __restrict__ off1, int* __restrict__ cur1,
                           const int* __restrict__ cnt2, int* __restrict__ off2, int* __restrict__ cur2) {
    const int* cnt = blockIdx.x ? cnt2 : cnt1;
    int* off = blockIdx.x ? off2 : off1;
    int* cur = blockIdx.x ? cur2 : cur1;
    int n = blockIdx.x ? N2_DST : N1_DST;

    __shared__ int wsum[32];
    __shared__ int carry_s;
    int tid = threadIdx.x, lane = tid & 31, w = tid >> 5;
    if (tid == 0) carry_s = 0;
    __syncthreads();
    for (int base = 0; base < n; base += 1024) {
        int i = base + tid;
        int v = (i < n) ? cnt[i] : 0;
        int x = v;
#pragma unroll
        for (int s = 1; s < 32; s <<= 1) {
            int t = __shfl_up_sync(0xFFFFFFFFu, x, s);
            if (lane >= s) x += t;
        }
        if (lane == 31) wsum[w] = x;
        __syncthreads();
        if (w == 0) {
            int y = wsum[lane];
#pragma unroll
            for (int s = 1; s < 32; s <<= 1) {
                int t = __shfl_up_sync(0xFFFFFFFFu, y, s);
                if (lane >= s) y += t;
            }
            wsum[lane] = y;
        }
        __syncthreads();
        int warp_excl = (w == 0) ? 0 : wsum[w - 1];
        int incl = carry_s + warp_excl + x;
        if (i < n) { off[i] = incl - v; cur[i] = incl - v; }
        __syncthreads();
        if (tid == 1023) carry_s = incl;
        __syncthreads();
    }
    if (threadIdx.x == 0) off[n] = carry_s;
}

__global__ void scatter_all_k(const int* __restrict__ es1, const int* __restrict__ ed1,
                              int* __restrict__ cur1, int* __restrict__ srt1,
                              const int* __restrict__ es2, const int* __restrict__ ed2,
                              int* __restrict__ cur2, int* __restrict__ srt2) {
    int i = blockIdx.x * blockDim.x + threadIdx.x;
    if (i < E1) {
        int p = atomicAdd(&cur1[ed1[i]], 1);
        srt1[p] = es1[i];
    } else if (i < E1 + E2) {
        int j = i - E1;
        int p = atomicAdd(&cur2[ed2[j]], 1);
        srt2[p] = es2[j];
    }
}

// W [K,N] fp32 -> Wt hi/lo [N,K] bf16 split, both weight matrices in one launch
__global__ void wsplit_all_k(const float* __restrict__ W1,
                             __nv_bfloat16* __restrict__ t1hi, __nv_bfloat16* __restrict__ t1lo,
                             const float* __restrict__ W2,
                             __nv_bfloat16* __restrict__ t2hi, __nv_bfloat16* __restrict__ t2lo) {
    int i = blockIdx.x * blockDim.x + threadIdx.x;
    const float* W; __nv_bfloat16 *thi, *tlo; int N;
    if (i < D * D) { W = W1; thi = t1hi; tlo = t1lo; N = D; }
    else if (i < D * D + DOUT * D) { i -= D * D; W = W2; thi = t2hi; tlo = t2lo; N = DOUT; }
    else return;
    int n = i / D, k = i - n * D;
    float v = W[(size_t)k * N + n];
    __nv_bfloat16 h = __float2bfloat16_rn(v);
    float r = v - __bfloat162float(h);
    thi[i] = h;
    tlo[i] = __float2bfloat16_rn(r);
}

// ---------------- aggregation: one CTA (128 threads) per dst node, bf16 split out ----------------
__global__ void __launch_bounds__(128)
agg_split_k(const float* __restrict__ feat, const int* __restrict__ off,
            const int* __restrict__ srt,
            __nv_bfloat16* __restrict__ ahi, __nv_bfloat16* __restrict__ alo) {
    int node = blockIdx.x;
    int t = threadIdx.x;                  // covers cols t*4 .. t*4+3
    const float4* fp = (const float4*)feat;
    int b = off[node], e = off[node + 1];

    float4 acc = fp[(size_t)node * (D / 4) + t];
    int j = b;
    for (; j + 3 < e; j += 4) {
        int s0 = srt[j], s1 = srt[j + 1], s2 = srt[j + 2], s3 = srt[j + 3];
        float4 v0 = fp[(size_t)s0 * (D / 4) + t];
        float4 v1 = fp[(size_t)s1 * (D / 4) + t];
        float4 v2 = fp[(size_t)s2 * (D / 4) + t];
        float4 v3 = fp[(size_t)s3 * (D / 4) + t];
        acc.x += v0.x + v1.x + v2.x + v3.x;
        acc.y += v0.y + v1.y + v2.y + v3.y;
        acc.z += v0.z + v1.z + v2.z + v3.z;
        acc.w += v0.w + v1.w + v2.w + v3.w;
    }
    for (; j < e; j++) {
        int s0 = srt[j];
        float4 v0 = fp[(size_t)s0 * (D / 4) + t];
        acc.x += v0.x; acc.y += v0.y; acc.z += v0.z; acc.w += v0.w;
    }
    float sc = 1.0f / (float)(e - b + 1);
    float v[4] = { acc.x * sc, acc.y * sc, acc.z * sc, acc.w * sc };

    ushort4 hi, lo;
    __nv_bfloat16 h;
    h = __float2bfloat16_rn(v[0]); hi.x = __bfloat16_as_ushort(h);
    lo.x = __bfloat16_as_ushort(__float2bfloat16_rn(v[0] - __bfloat162float(h)));
    h = __float2bfloat16_rn(v[1]); hi.y = __bfloat16_as_ushort(h);
    lo.y = __bfloat16_as_ushort(__float2bfloat16_rn(v[1] - __bfloat162float(h)));
    h = __float2bfloat16_rn(v[2]); hi.z = __bfloat16_as_ushort(h);
    lo.z = __bfloat16_as_ushort(__float2bfloat16_rn(v[2] - __bfloat162float(h)));
    h = __float2bfloat16_rn(v[3]); hi.w = __bfloat16_as_ushort(h);
    lo.w = __bfloat16_as_ushort(__float2bfloat16_rn(v[3] - __bfloat162float(h)));

    ((ushort4*)ahi)[(size_t)node * (D / 4) + t] = hi;
    ((ushort4*)alo)[(size_t)node * (D / 4) + t] = lo;
}

// ---------------- HMMA split-bf16 GEMM (templated tiles) ----------------
// C[M,N] = (Ahi+Alo)[M,K=512] @ (Bhi+Blo)^T + bias (opt relu)
// A: [M,512] bf16 row-major (hi/lo). B: [N,512] bf16 row-major.
// BK=32, warp tile (BM/TM)x(BN/TN), 80B padded smem rows (conflict-free ldmatrix),
// cp.async double-buffered.
#define ROWB 80                           // 32 bf16 = 64B + 16B pad

template <int BM, int BN, int TM, int TN>
__global__ void __launch_bounds__(TM * TN * 32, 1)
gemm_hmma_k(const __nv_bfloat16* __restrict__ Ahi, const __nv_bfloat16* __restrict__ Alo,
            const __nv_bfloat16* __restrict__ Bhi, const __nv_bfloat16* __restrict__ Blo,
            const float* __restrict__ bias, float* __restrict__ C,
            int ldc, int relu) {
    constexpr int THREADS = TM * TN * 32;
    constexpr int WM = BM / TM;           // warp tile M (32)
    constexpr int WN = BN / TN;           // warp tile N (64 or 32)
    constexpr int MT = WM / 16;           // 2
    constexpr int NG = WN / 16;           // 4 or 2
    constexpr int NT = WN / 8;            // 8 or 4
    constexpr int TOTROWS = 2 * BM + 2 * BN;
    constexpr int STAGE = TOTROWS * ROWB;
    constexpr int OPS = TOTROWS * 4 / THREADS;   // cp16 per thread per chunk

    extern __shared__ char smem[];
    uint32_t sm = smem_u32(smem);
    int tid = threadIdx.x;
    int wid = tid >> 5, lane = tid & 31;
    int wm = wid % TM;
    int wn = wid / TM;
    int m0 = blockIdx.y * BM;
    int n0 = blockIdx.x * BN;

    const char* gAh = (const char*)(Ahi + (size_t)m0 * D);
    const char* gAl = (const char*)(Alo + (size_t)m0 * D);
    const char* gBh = (const char*)(Bhi + (size_t)n0 * D);
    const char* gBl = (const char*)(Blo + (size_t)n0 * D);

    auto issue = [&](uint32_t st, int kc) {
#pragma unroll
        for (int j = 0; j < OPS; j++) {
            int i = tid + j * THREADS;
            int g = i >> 2;
            int c16 = i & 3;
            const char* src;
            if (g < BM)               src = gAh + (size_t)g * (D * 2);
            else if (g < 2 * BM)      src = gAl + (size_t)(g - BM) * (D * 2);
            else if (g < 2 * BM + BN) src = gBh + (size_t)(g - 2 * BM) * (D * 2);
            else                      src = gBl + (size_t)(g - 2 * BM - BN) * (D * 2);
            cp16(st + g * ROWB + c16 * 16, src + kc * 64 + c16 * 16);
        }
        cp_commit();
    };

    float acc[MT][NT][4];
#pragma unroll
    for (int mt = 0; mt < MT; mt++)
#pragma unroll
        for (int nt = 0; nt < NT; nt++)
#pragma unroll
            for (int r = 0; r < 4; r++) acc[mt][nt][r] = 0.0f;

    const int NCH = D / 32;               // 16
    issue(sm, 0);

    int a_row = wm * WM + (lane & 15);
    int a_kb = (lane >> 4) * 16;
    int b_row = wn * WN + ((lane >> 4) & 1) * 8 + (lane & 7);
    int b_kb = ((lane >> 3) & 1) * 16;

    for (int c = 0; c < NCH; c++) {
        uint32_t st = sm + (c & 1) * STAGE;
        if (c + 1 < NCH) {
            issue(sm + ((c + 1) & 1) * STAGE, c + 1);
            cp_wait<1>();
        } else {
            cp_wait<0>();
        }
        __syncthreads();

        uint32_t sAh = st;
        uint32_t sAl = st + BM * ROWB;
        uint32_t sBh = st + 2 * BM * ROWB;
        uint32_t sBl = sBh + BN * ROWB;

#pragma unroll
        for (int kk = 0; kk < 2; kk++) {
            uint32_t ah[MT][4], al[MT][4];
#pragma unroll
            for (int mt = 0; mt < MT; mt++) {
                uint32_t ao = (a_row + mt * 16) * ROWB + kk * 32 + a_kb;
                ldm_x4(ah[mt], sAh + ao);
                ldm_x4(al[mt], sAl + ao);
            }
#pragma unroll
            for (int ng = 0; ng < NG; ng++) {
                uint32_t bh[4], bl[4];
                uint32_t bo = (b_row + ng * 16) * ROWB + kk * 32 + b_kb;
                ldm_x4(bh, sBh + bo);
                ldm_x4(bl, sBl + bo);
#pragma unroll
                for (int mt = 0; mt < MT; mt++) {
#pragma unroll
                    for (int hf = 0; hf < 2; hf++) {
                        int nt = ng * 2 + hf;
                        mma_bf16(acc[mt][nt], ah[mt], &bh[hf * 2]);
                        mma_bf16(acc[mt][nt], ah[mt], &bl[hf * 2]);
                        mma_bf16(acc[mt][nt], al[mt], &bh[hf * 2]);
                    }
                }
            }
        }
        __syncthreads();
    }

    // epilogue: direct global stores (float2 per fragment row)
#pragma unroll
    for (int mt = 0; mt < MT; mt++) {
        int row0 = m0 + wm * WM + mt * 16 + (lane >> 2);
#pragma unroll
        for (int nt = 0; nt < NT; nt++) {
            int col = n0 + wn * WN + nt * 8 + (lane & 3) * 2;
            float b0 = bias[col], b1 = bias[col + 1];
            float2 v0, v1;
            v0.x = acc[mt][nt][0] + b0; v0.y = acc[mt][nt][1] + b1;
            v1.x = acc[mt][nt][2] + b0; v1.y = acc[mt][nt][3] + b1;
            if (relu) {
                v0.x = fmaxf(v0.x, 0.f); v0.y = fmaxf(v0.y, 0.f);
                v1.x = fmaxf(v1.x, 0.f); v1.y = fmaxf(v1.y, 0.f);
            }
            *(float2*)&C[(size_t)row0 * ldc + col] = v0;
            *(float2*)&C[(size_t)(row0 + 8) * ldc + col] = v1;
        }
    }
}

// L1: 128x256 tile, 512 threads. L2: 64x128 tile, 256 threads.
#define SMEM_L1 (2 * (2 * 128 + 2 * 256) * ROWB)   // 122880
#define SMEM_L2 (2 * (2 * 64 + 2 * 128) * ROWB)    // 61440

// ---------------- launch ----------------
extern "C" void kernel_launch(void* const* d_in, const int* in_sizes, int n_in,
                              void* d_out, int out_size) {
    const float* feats = (const float*)d_in[0];
    const float* W1    = (const float*)d_in[1];
    const float* b1    = (const float*)d_in[2];
    const float* W2    = (const float*)d_in[3];
    const float* b2    = (const float*)d_in[4];
    const int*   es1   = (const int*)d_in[5];
    const int*   ed1   = (const int*)d_in[6];
    const int*   es2   = (const int*)d_in[7];
    const int*   ed2   = (const int*)d_in[8];
    float* out = (float*)d_out;

    float* h1;
    __nv_bfloat16 *a1hi, *a1lo, *a2hi, *a2lo, *w1hi, *w1lo, *w2hi, *w2lo;
    int *cnt1, *off1, *cur1, *srt1, *cnt2, *off2, *cur2, *srt2;
    cudaGetSymbolAddress((void**)&h1,   g_h1);
    cudaGetSymbolAddress((void**)&a1hi, g_a1hi);
    cudaGetSymbolAddress((void**)&a1lo, g_a1lo);
    cudaGetSymbolAddress((void**)&a2hi, g_a2hi);
    cudaGetSymbolAddress((void**)&a2lo, g_a2lo);
    cudaGetSymbolAddress((void**)&w1hi, g_w1hi);
    cudaGetSymbolAddress((void**)&w1lo, g_w1lo);
    cudaGetSymbolAddress((void**)&w2hi, g_w2hi);
    cudaGetSymbolAddress((void**)&w2lo, g_w2lo);
    cudaGetSymbolAddress((void**)&cnt1, g_cnt1);
    cudaGetSymbolAddress((void**)&off1, g_off1);
    cudaGetSymbolAddress((void**)&cur1, g_cur1);
    cudaGetSymbolAddress((void**)&srt1, g_srt1);
    cudaGetSymbolAddress((void**)&cnt2, g_cnt2);
    cudaGetSymbolAddress((void**)&off2, g_off2);
    cudaGetSymbolAddress((void**)&cur2, g_cur2);
    cudaGetSymbolAddress((void**)&srt2, g_srt2);

    cudaFuncSetAttribute((void*)gemm_hmma_k<128, 256, 4, 4>,
                         cudaFuncAttributeMaxDynamicSharedMemorySize, SMEM_L1);
    cudaFuncSetAttribute((void*)gemm_hmma_k<64, 128, 2, 4>,
                         cudaFuncAttributeMaxDynamicSharedMemorySize, SMEM_L2);

    // ---- CSR build + weight prep (fused, zeroing via memset nodes) ----
    cudaMemsetAsync(cnt1, 0, N1_DST * sizeof(int));
    cudaMemsetAsync(cnt2, 0, N2_DST * sizeof(int));
    hist_all_k<<<(E1 + E2 + 255) / 256, 256>>>(ed1, ed2, cnt1, cnt2);
    scan_all_k<<<2, 1024>>>(cnt1, off1, cur1, cnt2, off2, cur2);
    scatter_all_k<<<(E1 + E2 + 255) / 256, 256>>>(es1, ed1, cur1, srt1, es2, ed2, cur2, srt2);
    wsplit_all_k<<<(D * D + DOUT * D + 255) / 256, 256>>>(W1, w1hi, w1lo, W2, w2hi, w2lo);

    // ---- layer 1 ----
    agg_split_k<<<N1_DST, 128>>>(feats, off1, srt1, a1hi, a1lo);
    {
        dim3 grid(D / 256, N1_DST / 128);   // (2, 352)
        gemm_hmma_k<128, 256, 4, 4><<<grid, 512, SMEM_L1>>>(a1hi, a1lo, w1hi, w1lo, b1, h1, D, 1);
    }

    // ---- layer 2 ----
    agg_split_k<<<N2_DST, 128>>>(h1, off2, srt2, a2hi, a2lo);
    {
        dim3 grid(DOUT / 128, N2_DST / 64);  // (2, 64)
        gemm_hmma_k<64, 128, 2, 4><<<grid, 256, SMEM_L2>>>(a2hi, a2lo, w2hi, w2lo, b2, out, DOUT, 0);
    }
}

// round 5
// speedup vs baseline: 3.1619x; 1.1408x over previous
#include <cuda_runtime.h>
#include <cuda_fp16.h>
#include <cstdint>

// Problem constants
#define N1_SRC 495616
#define N1_DST 45056
#define E1     450560
#define N2_SRC 45056
#define N2_DST 4096
#define E2     40960
#define D      512
#define DOUT   256

// ---------------- device scratch ----------------
__device__ float g_h1[(size_t)N1_DST * D];            // layer-1 output (fp32)
__device__ __half g_a1h[(size_t)N1_DST * D];          // layer-1 A (single fp16)
__device__ __half g_a2hi[(size_t)N2_DST * D];         // layer-2 A hi/lo fp16
__device__ __half g_a2lo[(size_t)N2_DST * D];
__device__ __half g_w1hi[(size_t)D * D];              // W1^T [N=512,K=512] fp16 split
__device__ __half g_w1lo[(size_t)D * D];
__device__ __half g_w2hi[(size_t)DOUT * D];           // W2^T [N=256,K=512] fp16 split
__device__ __half g_w2lo[(size_t)DOUT * D];

__device__ int g_cnt[N1_DST + N2_DST];                // combined: one memset
__device__ int g_cur[N1_DST + N2_DST];
__device__ int g_off1[N1_DST + 1];
__device__ int g_srt1[E1];
__device__ int g_off2[N2_DST + 1];
__device__ int g_srt2[E2];

// ---------------- PTX helpers (base-target safe) ----------------
__device__ __forceinline__ uint32_t smem_u32(const void* p) {
    uint32_t a;
    asm("{ .reg .u64 t; cvta.to.shared.u64 t, %1; cvt.u32.u64 %0, t; }" : "=r"(a) : "l"(p));
    return a;
}
__device__ __forceinline__ void cp16(uint32_t s, const void* g) {
    asm volatile("cp.async.cg.shared.global [%0], [%1], 16;" :: "r"(s), "l"(g));
}
__device__ __forceinline__ void cp_commit() {
    asm volatile("cp.async.commit_group;" ::: "memory");
}
template <int N>
__device__ __forceinline__ void cp_wait() {
    asm volatile("cp.async.wait_group %0;" :: "n"(N) : "memory");
}
__device__ __forceinline__ void ldm_x4(uint32_t* r, uint32_t addr) {
    asm volatile("ldmatrix.sync.aligned.m8n8.x4.shared.b16 {%0,%1,%2,%3}, [%4];"
                 : "=r"(r[0]), "=r"(r[1]), "=r"(r[2]), "=r"(r[3]) : "r"(addr));
}
// D += A(f16) * B(f16), m16n8k16, fp32 accum
__device__ __forceinline__ void mma_f16(float* c, const uint32_t* a, const uint32_t* b) {
    asm volatile(
        "mma.sync.aligned.m16n8k16.row.col.f32.f16.f16.f32 "
        "{%0,%1,%2,%3}, {%4,%5,%6,%7}, {%8,%9}, {%0,%1,%2,%3};"
        : "+f"(c[0]), "+f"(c[1]), "+f"(c[2]), "+f"(c[3])
        : "r"(a[0]), "r"(a[1]), "r"(a[2]), "r"(a[3]), "r"(b[0]), "r"(b[1]));
}

// ---------------- prep kernels ----------------
// W [K,N] fp32 -> Wt hi/lo [N,K] fp16 split, both weight matrices in one launch
__global__ void wsplit_all_k(const float* __restrict__ W1,
                             __half* __restrict__ t1hi, __half* __restrict__ t1lo,
                             const float* __restrict__ W2,
                             __half* __restrict__ t2hi, __half* __restrict__ t2lo) {
    int i = blockIdx.x * blockDim.x + threadIdx.x;
    const float* W; __half *thi, *tlo; int N;
    if (i < D * D) { W = W1; thi = t1hi; tlo = t1lo; N = D; }
    else if (i < D * D + DOUT * D) { i -= D * D; W = W2; thi = t2hi; tlo = t2lo; N = DOUT; }
    else return;
    int n = i / D, k = i - n * D;
    float v = W[(size_t)k * N + n];
    __half h = __float2half_rn(v);
    float r = v - __half2float(h);
    thi[i] = h;
    tlo[i] = __float2half_rn(r);
}

__global__ void hist_all_k(const int* __restrict__ ed1, const int* __restrict__ ed2,
                           int* __restrict__ cnt) {
    int i = blockIdx.x * blockDim.x + threadIdx.x;
    if (i < E1) atomicAdd(&cnt[ed1[i]], 1);
    else if (i < E1 + E2) atomicAdd(&cnt[N1_DST + ed2[i - E1]], 1);
}

// per-block exclusive scan; block 0 -> layer1, block 1 -> layer2
__global__ void scan_all_k(const int* __restrict__ cnt, int* __restrict__ cur,
                           int* __restrict__ off1, int* __restrict__ off2) {
    const int* c = cnt + (blockIdx.x ? N1_DST : 0);
    int* cu = (int*)cur + (blockIdx.x ? N1_DST : 0);
    int* off = blockIdx.x ? off2 : off1;
    int n = blockIdx.x ? N2_DST : N1_DST;

    __shared__ int wsum[32];
    __shared__ int carry_s;
    int tid = threadIdx.x, lane = tid & 31, w = tid >> 5;
    if (tid == 0) carry_s = 0;
    __syncthreads();
    for (int base = 0; base < n; base += 1024) {
        int i = base + tid;
        int v = (i < n) ? c[i] : 0;
        int x = v;
#pragma unroll
        for (int s = 1; s < 32; s <<= 1) {
            int t = __shfl_up_sync(0xFFFFFFFFu, x, s);
            if (lane >= s) x += t;
        }
        if (lane == 31) wsum[w] = x;
        __syncthreads();
        if (w == 0) {
            int y = wsum[lane];
#pragma unroll
            for (int s = 1; s < 32; s <<= 1) {
                int t = __shfl_up_sync(0xFFFFFFFFu, y, s);
                if (lane >= s) y += t;
            }
            wsum[lane] = y;
        }
        __syncthreads();
        int warp_excl = (w == 0) ? 0 : wsum[w - 1];
        int incl = carry_s + warp_excl + x;
        if (i < n) { off[i] = incl - v; cu[i] = incl - v; }
        __syncthreads();
        if (tid == 1023) carry_s = incl;
        __syncthreads();
    }
    if (threadIdx.x == 0) off[n] = carry_s;
}

__global__ void scatter_all_k(const int* __restrict__ es1, const int* __restrict__ ed1,
                              const int* __restrict__ es2, const int* __restrict__ ed2,
                              int* __restrict__ cur,
                              int* __restrict__ srt1, int* __restrict__ srt2) {
    int i = blockIdx.x * blockDim.x + threadIdx.x;
    if (i < E1) {
        int p = atomicAdd(&cur[ed1[i]], 1);
        srt1[p] = es1[i];
    } else if (i < E1 + E2) {
        int j = i - E1;
        int p = atomicAdd(&cur[N1_DST + ed2[j]], 1);
        srt2[p] = es2[j];
    }
}

// ---------------- aggregation: one CTA (128 threads) per dst node ----------------
// LO=false: write single fp16 (layer 1). LO=true: write fp16 hi+lo (layer 2).
template <bool LO>
__global__ void __launch_bounds__(128)
agg_split_k(const float* __restrict__ feat, const int* __restrict__ off,
            const int* __restrict__ srt,
            __half* __restrict__ ahi, __half* __restrict__ alo) {
    int node = blockIdx.x;
    int t = threadIdx.x;                  // covers cols t*4 .. t*4+3
    const float4* fp = (const float4*)feat;
    int b = off[node], e = off[node + 1];

    float4 acc = fp[(size_t)node * (D / 4) + t];
    int j = b;
    for (; j + 3 < e; j += 4) {
        int s0 = srt[j], s1 = srt[j + 1], s2 = srt[j + 2], s3 = srt[j + 3];
        float4 v0 = fp[(size_t)s0 * (D / 4) + t];
        float4 v1 = fp[(size_t)s1 * (D / 4) + t];
        float4 v2 = fp[(size_t)s2 * (D / 4) + t];
        float4 v3 = fp[(size_t)s3 * (D / 4) + t];
        acc.x += v0.x + v1.x + v2.x + v3.x;
        acc.y += v0.y + v1.y + v2.y + v3.y;
        acc.z += v0.z + v1.z + v2.z + v3.z;
        acc.w += v0.w + v1.w + v2.w + v3.w;
    }
    for (; j < e; j++) {
        int s0 = srt[j];
        float4 v0 = fp[(size_t)s0 * (D / 4) + t];
        acc.x += v0.x; acc.y += v0.y; acc.z += v0.z; acc.w += v0.w;
    }
    float sc = 1.0f / (float)(e - b + 1);
    float v[4] = { acc.x * sc, acc.y * sc, acc.z * sc, acc.w * sc };

    uint32_t hi01, hi23;
    __half h0 = __float2half_rn(v[0]), h1 = __float2half_rn(v[1]);
    __half h2 = __float2half_rn(v[2]), h3 = __float2half_rn(v[3]);
    hi01 = (uint32_t)__half_as_ushort(h0) | ((uint32_t)__half_as_ushort(h1) << 16);
    hi23 = (uint32_t)__half_as_ushort(h2) | ((uint32_t)__half_as_ushort(h3) << 16);
    ((uint2*)ahi)[(size_t)node * (D / 4) + t] = make_uint2(hi01, hi23);

    if (LO) {
        uint32_t lo01, lo23;
        __half l0 = __float2half_rn(v[0] - __half2float(h0));
        __half l1 = __float2half_rn(v[1] - __half2float(h1));
        __half l2 = __float2half_rn(v[2] - __half2float(h2));
        __half l3 = __float2half_rn(v[3] - __half2float(h3));
        lo01 = (uint32_t)__half_as_ushort(l0) | ((uint32_t)__half_as_ushort(l1) << 16);
        lo23 = (uint32_t)__half_as_ushort(l2) | ((uint32_t)__half_as_ushort(l3) << 16);
        ((uint2*)alo)[(size_t)node * (D / 4) + t] = make_uint2(lo01, lo23);
    }
}

// ---------------- HMMA split-fp16 GEMM (templated) ----------------
// SPLITA=false: C = Ah @ (Bh+Bl)^T + bias    (2 MMAs/frag)
// SPLITA=true:  C = (Ah+Al) @ (Bh+Bl)^T + bias, drop Al*Bl (3 MMAs/frag)
// A: [M,512] fp16 row-major. B: [N,512] fp16 row-major (pre-transposed W).
// BK=32, 80B padded smem rows, cp.async double-buffered.
#define ROWB 80

template <int BM, int BN, int TM, int TN, bool SPLITA>
__global__ void __launch_bounds__(TM * TN * 32, 1)
gemm_hmma_k(const __half* __restrict__ Ah, const __half* __restrict__ Al,
            const __half* __restrict__ Bh, const __half* __restrict__ Bl,
            const float* __restrict__ bias, float* __restrict__ C,
            int ldc, int relu) {
    constexpr int THREADS = TM * TN * 32;
    constexpr int WM = BM / TM;
    constexpr int WN = BN / TN;
    constexpr int MT = WM / 16;
    constexpr int NG = WN / 16;
    constexpr int NT = WN / 8;
    constexpr int AROWS = SPLITA ? 2 * BM : BM;
    constexpr int TOTROWS = AROWS + 2 * BN;
    constexpr int STAGE = TOTROWS * ROWB;
    constexpr int OPS = TOTROWS * 4 / THREADS;

    extern __shared__ char smem[];
    uint32_t sm = smem_u32(smem);
    int tid = threadIdx.x;
    int wid = tid >> 5, lane = tid & 31;
    int wm = wid % TM;
    int wn = wid / TM;
    int m0 = blockIdx.y * BM;
    int n0 = blockIdx.x * BN;

    const char* gAh = (const char*)(Ah + (size_t)m0 * D);
    const char* gAl = SPLITA ? (const char*)(Al + (size_t)m0 * D) : gAh;
    const char* gBh = (const char*)(Bh + (size_t)n0 * D);
    const char* gBl = (const char*)(Bl + (size_t)n0 * D);

    auto issue = [&](uint32_t st, int kc) {
#pragma unroll
        for (int j = 0; j < OPS; j++) {
            int i = tid + j * THREADS;
            int g = i >> 2;
            int c16 = i & 3;
            const char* src;
            if (g < BM)                 src = gAh + (size_t)g * (D * 2);
            else if (SPLITA && g < 2 * BM) src = gAl + (size_t)(g - BM) * (D * 2);
            else if (g < AROWS + BN)    src = gBh + (size_t)(g - AROWS) * (D * 2);
            else                        src = gBl + (size_t)(g - AROWS - BN) * (D * 2);
            cp16(st + g * ROWB + c16 * 16, src + kc * 64 + c16 * 16);
        }
        cp_commit();
    };

    float acc[MT][NT][4];
#pragma unroll
    for (int mt = 0; mt < MT; mt++)
#pragma unroll
        for (int nt = 0; nt < NT; nt++)
#pragma unroll
            for (int r = 0; r < 4; r++) acc[mt][nt][r] = 0.0f;

    const int NCH = D / 32;               // 16
    issue(sm, 0);

    int a_row = wm * WM + (lane & 15);
    int a_kb = (lane >> 4) * 16;
    int b_row = wn * WN + ((lane >> 4) & 1) * 8 + (lane & 7);
    int b_kb = ((lane >> 3) & 1) * 16;

    for (int c = 0; c < NCH; c++) {
        uint32_t st = sm + (c & 1) * STAGE;
        if (c + 1 < NCH) {
            issue(sm + ((c + 1) & 1) * STAGE, c + 1);
            cp_wait<1>();
        } else {
            cp_wait<0>();
        }
        __syncthreads();

        uint32_t sAh = st;
        uint32_t sAl = st + BM * ROWB;
        uint32_t sBh = st + AROWS * ROWB;
        uint32_t sBl = sBh + BN * ROWB;

#pragma unroll
        for (int kk = 0; kk < 2; kk++) {
            uint32_t ah[MT][4], al[MT][4];
#pragma unroll
            for (int mt = 0; mt < MT; mt++) {
                uint32_t ao = (a_row + mt * 16) * ROWB + kk * 32 + a_kb;
                ldm_x4(ah[mt], sAh + ao);
                if (SPLITA) ldm_x4(al[mt], sAl + ao);
            }
#pragma unroll
            for (int ng = 0; ng < NG; ng++) {
                uint32_t bh[4], bl[4];
                uint32_t bo = (b_row + ng * 16) * ROWB + kk * 32 + b_kb;
                ldm_x4(bh, sBh + bo);
                ldm_x4(bl, sBl + bo);
#pragma unroll
                for (int mt = 0; mt < MT; mt++) {
#pragma unroll
                    for (int hf = 0; hf < 2; hf++) {
                        int nt = ng * 2 + hf;
                        mma_f16(acc[mt][nt], ah[mt], &bh[hf * 2]);
                        mma_f16(acc[mt][nt], ah[mt], &bl[hf * 2]);
                        if (SPLITA) mma_f16(acc[mt][nt], al[mt], &bh[hf * 2]);
                    }
                }
            }
        }
        __syncthreads();
    }

    // epilogue: direct global stores
#pragma unroll
    for (int mt = 0; mt < MT; mt++) {
        int row0 = m0 + wm * WM + mt * 16 + (lane >> 2);
#pragma unroll
        for (int nt = 0; nt < NT; nt++) {
            int col = n0 + wn * WN + nt * 8 + (lane & 3) * 2;
            float b0 = bias[col], b1 = bias[col + 1];
            float2 v0, v1;
            v0.x = acc[mt][nt][0] + b0; v0.y = acc[mt][nt][1] + b1;
            v1.x = acc[mt][nt][2] + b0; v1.y = acc[mt][nt][3] + b1;
            if (relu) {
                v0.x = fmaxf(v0.x, 0.f); v0.y = fmaxf(v0.y, 0.f);
                v1.x = fmaxf(v1.x, 0.f); v1.y = fmaxf(v1.y, 0.f);
            }
            *(float2*)&C[(size_t)row0 * ldc + col] = v0;
            *(float2*)&C[(size_t)(row0 + 8) * ldc + col] = v1;
        }
    }
}

// L1: 128x256 tile, 512 threads, A single.   smem = 2*(128+512)*80 = 102400
// L2: 64x128 tile, 256 threads, A split.     smem = 2*(128+256)*80 = 61440
#define SMEM_L1 (2 * (128 + 2 * 256) * ROWB)
#define SMEM_L2 (2 * (2 * 64 + 2 * 128) * ROWB)

// ---------------- launch ----------------
extern "C" void kernel_launch(void* const* d_in, const int* in_sizes, int n_in,
                              void* d_out, int out_size) {
    const float* feats = (const float*)d_in[0];
    const float* W1    = (const float*)d_in[1];
    const float* b1    = (const float*)d_in[2];
    const float* W2    = (const float*)d_in[3];
    const float* b2    = (const float*)d_in[4];
    const int*   es1   = (const int*)d_in[5];
    const int*   ed1   = (const int*)d_in[6];
    const int*   es2   = (const int*)d_in[7];
    const int*   ed2   = (const int*)d_in[8];
    float* out = (float*)d_out;

    float* h1;
    __half *a1h, *a2hi, *a2lo, *w1hi, *w1lo, *w2hi, *w2lo;
    int *cnt, *cur, *off1, *srt1, *off2, *srt2;
    cudaGetSymbolAddress((void**)&h1,   g_h1);
    cudaGetSymbolAddress((void**)&a1h,  g_a1h);
    cudaGetSymbolAddress((void**)&a2hi, g_a2hi);
    cudaGetSymbolAddress((void**)&a2lo, g_a2lo);
    cudaGetSymbolAddress((void**)&w1hi, g_w1hi);
    cudaGetSymbolAddress((void**)&w1lo, g_w1lo);
    cudaGetSymbolAddress((void**)&w2hi, g_w2hi);
    cudaGetSymbolAddress((void**)&w2lo, g_w2lo);
    cudaGetSymbolAddress((void**)&cnt,  g_cnt);
    cudaGetSymbolAddress((void**)&cur,  g_cur);
    cudaGetSymbolAddress((void**)&off1, g_off1);
    cudaGetSymbolAddress((void**)&srt1, g_srt1);
    cudaGetSymbolAddress((void**)&off2, g_off2);
    cudaGetSymbolAddress((void**)&srt2, g_srt2);

    cudaFuncSetAttribute((void*)gemm_hmma_k<128, 256, 4, 4, false>,
                         cudaFuncAttributeMaxDynamicSharedMemorySize, SMEM_L1);
    cudaFuncSetAttribute((void*)gemm_hmma_k<64, 128, 2, 4, true>,
                         cudaFuncAttributeMaxDynamicSharedMemorySize, SMEM_L2);

    // launch order puts agg_split(layer1) at kernel index 5 for the ncu -s 5 window
    wsplit_all_k<<<(D * D + DOUT * D + 255) / 256, 256>>>(W1, w1hi, w1lo, W2, w2hi, w2lo);  // 0
    cudaMemsetAsync(cnt, 0, (N1_DST + N2_DST) * sizeof(int));                               // 1
    hist_all_k<<<(E1 + E2 + 255) / 256, 256>>>(ed1, ed2, cnt);                              // 2
    scan_all_k<<<2, 1024>>>(cnt, cur, off1, off2);                                          // 3
    scatter_all_k<<<(E1 + E2 + 255) / 256, 256>>>(es1, ed1, es2, ed2, cur, srt1, srt2);     // 4

    // ---- layer 1 ----
    agg_split_k<false><<<N1_DST, 128>>>(feats, off1, srt1, a1h, nullptr);                   // 5
    {
        dim3 grid(D / 256, N1_DST / 128);   // (2, 352)
        gemm_hmma_k<128, 256, 4, 4, false><<<grid, 512, SMEM_L1>>>(
            a1h, nullptr, w1hi, w1lo, b1, h1, D, 1);                                        // 6
    }

    // ---- layer 2 ----
    agg_split_k<true><<<N2_DST, 128>>>(h1, off2, srt2, a2hi, a2lo);                         // 7
    {
        dim3 grid(DOUT / 128, N2_DST / 64);  // (2, 64)
        gemm_hmma_k<64, 128, 2, 4, true><<<grid, 256, SMEM_L2>>>(
            a2hi, a2lo, w2hi, w2lo, b2, out, DOUT, 0);                                      // 8
    }
}

// round 6
// speedup vs baseline: 3.7663x; 1.1912x over previous
#include <cuda_runtime.h>
#include <cuda_fp16.h>
#include <cstdint>

// Problem constants
#define N1_SRC 495616
#define N1_DST 45056
#define E1     450560
#define N2_SRC 45056
#define N2_DST 4096
#define E2     40960
#define D      512
#define DOUT   256

// ---------------- device scratch ----------------
__device__ float g_h1[(size_t)N1_DST * D];            // layer-1 output (fp32)
__device__ __half g_a1h[(size_t)N1_DST * D];          // layer-1 A (single fp16)
__device__ __half g_a2hi[(size_t)N2_DST * D];         // layer-2 A hi/lo fp16
__device__ __half g_a2lo[(size_t)N2_DST * D];
__device__ __half g_w1hi[(size_t)D * D];              // W1^T [N=512,K=512] fp16
__device__ __half g_w1lo[(size_t)D * D];
__device__ __half g_w2hi[(size_t)DOUT * D];           // W2^T [N=256,K=512] fp16 split
__device__ __half g_w2lo[(size_t)DOUT * D];

__device__ int g_cnt[N1_DST + N2_DST];                // combined: one memset
__device__ int g_cur[N1_DST + N2_DST];
__device__ int g_off1[N1_DST + 1];
__device__ int g_srt1[E1];
__device__ int g_off2[N2_DST + 1];
__device__ int g_srt2[E2];

// ---------------- PTX helpers (base-target safe) ----------------
__device__ __forceinline__ uint32_t smem_u32(const void* p) {
    uint32_t a;
    asm("{ .reg .u64 t; cvta.to.shared.u64 t, %1; cvt.u32.u64 %0, t; }" : "=r"(a) : "l"(p));
    return a;
}
__device__ __forceinline__ void cp16(uint32_t s, const void* g) {
    asm volatile("cp.async.cg.shared.global [%0], [%1], 16;" :: "r"(s), "l"(g));
}
__device__ __forceinline__ void cp_commit() {
    asm volatile("cp.async.commit_group;" ::: "memory");
}
template <int N>
__device__ __forceinline__ void cp_wait() {
    asm volatile("cp.async.wait_group %0;" :: "n"(N) : "memory");
}
__device__ __forceinline__ void ldm_x4(uint32_t* r, uint32_t addr) {
    asm volatile("ldmatrix.sync.aligned.m8n8.x4.shared.b16 {%0,%1,%2,%3}, [%4];"
                 : "=r"(r[0]), "=r"(r[1]), "=r"(r[2]), "=r"(r[3]) : "r"(addr));
}
// D += A(f16) * B(f16), m16n8k16, fp32 accum
__device__ __forceinline__ void mma_f16(float* c, const uint32_t* a, const uint32_t* b) {
    asm volatile(
        "mma.sync.aligned.m16n8k16.row.col.f32.f16.f16.f32 "
        "{%0,%1,%2,%3}, {%4,%5,%6,%7}, {%8,%9}, {%0,%1,%2,%3};"
        : "+f"(c[0]), "+f"(c[1]), "+f"(c[2]), "+f"(c[3])
        : "r"(a[0]), "r"(a[1]), "r"(a[2]), "r"(a[3]), "r"(b[0]), "r"(b[1]));
}

// ---------------- prep kernels ----------------
// W [K,N] fp32 -> Wt hi/lo [N,K] fp16 split, both weight matrices in one launch
__global__ void wsplit_all_k(const float* __restrict__ W1,
                             __half* __restrict__ t1hi, __half* __restrict__ t1lo,
                             const float* __restrict__ W2,
                             __half* __restrict__ t2hi, __half* __restrict__ t2lo) {
    int i = blockIdx.x * blockDim.x + threadIdx.x;
    const float* W; __half *thi, *tlo; int N;
    if (i < D * D) { W = W1; thi = t1hi; tlo = t1lo; N = D; }
    else if (i < D * D + DOUT * D) { i -= D * D; W = W2; thi = t2hi; tlo = t2lo; N = DOUT; }
    else return;
    int n = i / D, k = i - n * D;
    float v = W[(size_t)k * N + n];
    __half h = __float2half_rn(v);
    float r = v - __half2float(h);
    thi[i] = h;
    tlo[i] = __float2half_rn(r);
}

__global__ void hist_all_k(const int* __restrict__ ed1, const int* __restrict__ ed2,
                           int* __restrict__ cnt) {
    int i = blockIdx.x * blockDim.x + threadIdx.x;
    if (i < E1) atomicAdd(&cnt[ed1[i]], 1);
    else if (i < E1 + E2) atomicAdd(&cnt[N1_DST + ed2[i - E1]], 1);
}

// per-block exclusive scan; block 0 -> layer1, block 1 -> layer2
__global__ void scan_all_k(const int* __restrict__ cnt, int* __restrict__ cur,
                           int* __restrict__ off1, int* __restrict__ off2) {
    const int* c = cnt + (blockIdx.x ? N1_DST : 0);
    int* cu = (int*)cur + (blockIdx.x ? N1_DST : 0);
    int* off = blockIdx.x ? off2 : off1;
    int n = blockIdx.x ? N2_DST : N1_DST;

    __shared__ int wsum[32];
    __shared__ int carry_s;
    int tid = threadIdx.x, lane = tid & 31, w = tid >> 5;
    if (tid == 0) carry_s = 0;
    __syncthreads();
    for (int base = 0; base < n; base += 1024) {
        int i = base + tid;
        int v = (i < n) ? c[i] : 0;
        int x = v;
#pragma unroll
        for (int s = 1; s < 32; s <<= 1) {
            int t = __shfl_up_sync(0xFFFFFFFFu, x, s);
            if (lane >= s) x += t;
        }
        if (lane == 31) wsum[w] = x;
        __syncthreads();
        if (w == 0) {
            int y = wsum[lane];
#pragma unroll
            for (int s = 1; s < 32; s <<= 1) {
                int t = __shfl_up_sync(0xFFFFFFFFu, y, s);
                if (lane >= s) y += t;
            }
            wsum[lane] = y;
        }
        __syncthreads();
        int warp_excl = (w == 0) ? 0 : wsum[w - 1];
        int incl = carry_s + warp_excl + x;
        if (i < n) { off[i] = incl - v; cu[i] = incl - v; }
        __syncthreads();
        if (tid == 1023) carry_s = incl;
        __syncthreads();
    }
    if (threadIdx.x == 0) off[n] = carry_s;
}

__global__ void scatter_all_k(const int* __restrict__ es1, const int* __restrict__ ed1,
                              const int* __restrict__ es2, const int* __restrict__ ed2,
                              int* __restrict__ cur,
                              int* __restrict__ srt1, int* __restrict__ srt2) {
    int i = blockIdx.x * blockDim.x + threadIdx.x;
    if (i < E1) {
        int p = atomicAdd(&cur[ed1[i]], 1);
        srt1[p] = es1[i];
    } else if (i < E1 + E2) {
        int j = i - E1;
        int p = atomicAdd(&cur[N1_DST + ed2[j]], 1);
        srt2[p] = es2[j];
    }
}

// ---------------- aggregation: one CTA (128 threads) per dst node ----------------
// LO=false: write single fp16 (layer 1). LO=true: write fp16 hi+lo (layer 2).
template <bool LO>
__global__ void __launch_bounds__(128)
agg_split_k(const float* __restrict__ feat, const int* __restrict__ off,
            const int* __restrict__ srt,
            __half* __restrict__ ahi, __half* __restrict__ alo) {
    int node = blockIdx.x;
    int t = threadIdx.x;                  // covers cols t*4 .. t*4+3
    const float4* fp = (const float4*)feat;
    int b = off[node], e = off[node + 1];

    float4 acc = fp[(size_t)node * (D / 4) + t];
    int j = b;
    for (; j + 3 < e; j += 4) {
        int s0 = srt[j], s1 = srt[j + 1], s2 = srt[j + 2], s3 = srt[j + 3];
        float4 v0 = fp[(size_t)s0 * (D / 4) + t];
        float4 v1 = fp[(size_t)s1 * (D / 4) + t];
        float4 v2 = fp[(size_t)s2 * (D / 4) + t];
        float4 v3 = fp[(size_t)s3 * (D / 4) + t];
        acc.x += v0.x + v1.x + v2.x + v3.x;
        acc.y += v0.y + v1.y + v2.y + v3.y;
        acc.z += v0.z + v1.z + v2.z + v3.z;
        acc.w += v0.w + v1.w + v2.w + v3.w;
    }
    for (; j < e; j++) {
        int s0 = srt[j];
        float4 v0 = fp[(size_t)s0 * (D / 4) + t];
        acc.x += v0.x; acc.y += v0.y; acc.z += v0.z; acc.w += v0.w;
    }
    float sc = 1.0f / (float)(e - b + 1);
    float v[4] = { acc.x * sc, acc.y * sc, acc.z * sc, acc.w * sc };

    uint32_t hi01, hi23;
    __half h0 = __float2half_rn(v[0]), h1 = __float2half_rn(v[1]);
    __half h2 = __float2half_rn(v[2]), h3 = __float2half_rn(v[3]);
    hi01 = (uint32_t)__half_as_ushort(h0) | ((uint32_t)__half_as_ushort(h1) << 16);
    hi23 = (uint32_t)__half_as_ushort(h2) | ((uint32_t)__half_as_ushort(h3) << 16);
    ((uint2*)ahi)[(size_t)node * (D / 4) + t] = make_uint2(hi01, hi23);

    if (LO) {
        uint32_t lo01, lo23;
        __half l0 = __float2half_rn(v[0] - __half2float(h0));
        __half l1 = __float2half_rn(v[1] - __half2float(h1));
        __half l2 = __float2half_rn(v[2] - __half2float(h2));
        __half l3 = __float2half_rn(v[3] - __half2float(h3));
        lo01 = (uint32_t)__half_as_ushort(l0) | ((uint32_t)__half_as_ushort(l1) << 16);
        lo23 = (uint32_t)__half_as_ushort(l2) | ((uint32_t)__half_as_ushort(l3) << 16);
        ((uint2*)alo)[(size_t)node * (D / 4) + t] = make_uint2(lo01, lo23);
    }
}

// ---------------- HMMA fp16 GEMM (templated split config) ----------------
// C = sum of selected terms over {Ah,Al} x {Bh,Bl}^T + bias (opt relu):
//   always Ah*Bh; +Ah*Bl if SPLITB; +Al*Bh if SPLITA.
// A: [M,512] fp16 row-major. B: [N,512] fp16 row-major (pre-transposed W).
// BK=32, 80B padded smem rows, cp.async double-buffered.
#define ROWB 80

template <int BM, int BN, int TM, int TN, bool SPLITA, bool SPLITB>
__global__ void __launch_bounds__(TM * TN * 32, 1)
gemm_hmma_k(const __half* __restrict__ Ah, const __half* __restrict__ Al,
            const __half* __restrict__ Bh, const __half* __restrict__ Bl,
            const float* __restrict__ bias, float* __restrict__ C,
            int ldc, int relu) {
    constexpr int THREADS = TM * TN * 32;
    constexpr int WM = BM / TM;
    constexpr int WN = BN / TN;
    constexpr int MT = WM / 16;
    constexpr int NG = WN / 16;
    constexpr int NT = WN / 8;
    constexpr int AROWS = SPLITA ? 2 * BM : BM;
    constexpr int BROWS = SPLITB ? 2 * BN : BN;
    constexpr int TOTROWS = AROWS + BROWS;
    constexpr int STAGE = TOTROWS * ROWB;
    constexpr int OPS = TOTROWS * 4 / THREADS;

    extern __shared__ char smem[];
    uint32_t sm = smem_u32(smem);
    int tid = threadIdx.x;
    int wid = tid >> 5, lane = tid & 31;
    int wm = wid % TM;
    int wn = wid / TM;
    int m0 = blockIdx.y * BM;
    int n0 = blockIdx.x * BN;

    const char* gAh = (const char*)(Ah + (size_t)m0 * D);
    const char* gAl = SPLITA ? (const char*)(Al + (size_t)m0 * D) : gAh;
    const char* gBh = (const char*)(Bh + (size_t)n0 * D);
    const char* gBl = SPLITB ? (const char*)(Bl + (size_t)n0 * D) : gBh;

    auto issue = [&](uint32_t st, int kc) {
#pragma unroll
        for (int j = 0; j < OPS; j++) {
            int i = tid + j * THREADS;
            int g = i >> 2;
            int c16 = i & 3;
            const char* src;
            if (g < BM)                    src = gAh + (size_t)g * (D * 2);
            else if (SPLITA && g < 2 * BM) src = gAl + (size_t)(g - BM) * (D * 2);
            else if (g < AROWS + BN)       src = gBh + (size_t)(g - AROWS) * (D * 2);
            else                           src = gBl + (size_t)(g - AROWS - BN) * (D * 2);
            cp16(st + g * ROWB + c16 * 16, src + kc * 64 + c16 * 16);
        }
        cp_commit();
    };

    float acc[MT][NT][4];
#pragma unroll
    for (int mt = 0; mt < MT; mt++)
#pragma unroll
        for (int nt = 0; nt < NT; nt++)
#pragma unroll
            for (int r = 0; r < 4; r++) acc[mt][nt][r] = 0.0f;

    const int NCH = D / 32;               // 16
    issue(sm, 0);

    int a_row = wm * WM + (lane & 15);
    int a_kb = (lane >> 4) * 16;
    int b_row = wn * WN + ((lane >> 4) & 1) * 8 + (lane & 7);
    int b_kb = ((lane >> 3) & 1) * 16;

    for (int c = 0; c < NCH; c++) {
        uint32_t st = sm + (c & 1) * STAGE;
        if (c + 1 < NCH) {
            issue(sm + ((c + 1) & 1) * STAGE, c + 1);
            cp_wait<1>();
        } else {
            cp_wait<0>();
        }
        __syncthreads();

        uint32_t sAh = st;
        uint32_t sAl = st + BM * ROWB;
        uint32_t sBh = st + AROWS * ROWB;
        uint32_t sBl = sBh + BN * ROWB;

#pragma unroll
        for (int kk = 0; kk < 2; kk++) {
            uint32_t ah[MT][4], al[MT][4];
#pragma unroll
            for (int mt = 0; mt < MT; mt++) {
                uint32_t ao = (a_row + mt * 16) * ROWB + kk * 32 + a_kb;
                ldm_x4(ah[mt], sAh + ao);
                if (SPLITA) ldm_x4(al[mt], sAl + ao);
            }
#pragma unroll
            for (int ng = 0; ng < NG; ng++) {
                uint32_t bh[4], bl[4];
                uint32_t bo = (b_row + ng * 16) * ROWB + kk * 32 + b_kb;
                ldm_x4(bh, sBh + bo);
                if (SPLITB) ldm_x4(bl, sBl + bo);
#pragma unroll
                for (int mt = 0; mt < MT; mt++) {
#pragma unroll
                    for (int hf = 0; hf < 2; hf++) {
                        int nt = ng * 2 + hf;
                        mma_f16(acc[mt][nt], ah[mt], &bh[hf * 2]);
                        if (SPLITB) mma_f16(acc[mt][nt], ah[mt], &bl[hf * 2]);
                        if (SPLITA) mma_f16(acc[mt][nt], al[mt], &bh[hf * 2]);
                    }
                }
            }
        }
        __syncthreads();
    }

    // epilogue: direct global stores
#pragma unroll
    for (int mt = 0; mt < MT; mt++) {
        int row0 = m0 + wm * WM + mt * 16 + (lane >> 2);
#pragma unroll
        for (int nt = 0; nt < NT; nt++) {
            int col = n0 + wn * WN + nt * 8 + (lane & 3) * 2;
            float b0 = bias[col], b1 = bias[col + 1];
            float2 v0, v1;
            v0.x = acc[mt][nt][0] + b0; v0.y = acc[mt][nt][1] + b1;
            v1.x = acc[mt][nt][2] + b0; v1.y = acc[mt][nt][3] + b1;
            if (relu) {
                v0.x = fmaxf(v0.x, 0.f); v0.y = fmaxf(v0.y, 0.f);
                v1.x = fmaxf(v1.x, 0.f); v1.y = fmaxf(v1.y, 0.f);
            }
            *(float2*)&C[(size_t)row0 * ldc + col] = v0;
            *(float2*)&C[(size_t)(row0 + 8) * ldc + col] = v1;
        }
    }
}

// L1: 128x256 tile, 512 threads, single x single.  smem = 2*(128+256)*80 = 61440
// L2: 64x128 tile, 256 threads, split x split.     smem = 2*(128+256)*80 = 61440
#define SMEM_L1 (2 * (128 + 256) * ROWB)
#define SMEM_L2 (2 * (2 * 64 + 2 * 128) * ROWB)

// ---------------- launch ----------------
extern "C" void kernel_launch(void* const* d_in, const int* in_sizes, int n_in,
                              void* d_out, int out_size) {
    const float* feats = (const float*)d_in[0];
    const float* W1    = (const float*)d_in[1];
    const float* b1    = (const float*)d_in[2];
    const float* W2    = (const float*)d_in[3];
    const float* b2    = (const float*)d_in[4];
    const int*   es1   = (const int*)d_in[5];
    const int*   ed1   = (const int*)d_in[6];
    const int*   es2   = (const int*)d_in[7];
    const int*   ed2   = (const int*)d_in[8];
    float* out = (float*)d_out;

    float* h1;
    __half *a1h, *a2hi, *a2lo, *w1hi, *w1lo, *w2hi, *w2lo;
    int *cnt, *cur, *off1, *srt1, *off2, *srt2;
    cudaGetSymbolAddress((void**)&h1,   g_h1);
    cudaGetSymbolAddress((void**)&a1h,  g_a1h);
    cudaGetSymbolAddress((void**)&a2hi, g_a2hi);
    cudaGetSymbolAddress((void**)&a2lo, g_a2lo);
    cudaGetSymbolAddress((void**)&w1hi, g_w1hi);
    cudaGetSymbolAddress((void**)&w1lo, g_w1lo);
    cudaGetSymbolAddress((void**)&w2hi, g_w2hi);
    cudaGetSymbolAddress((void**)&w2lo, g_w2lo);
    cudaGetSymbolAddress((void**)&cnt,  g_cnt);
    cudaGetSymbolAddress((void**)&cur,  g_cur);
    cudaGetSymbolAddress((void**)&off1, g_off1);
    cudaGetSymbolAddress((void**)&srt1, g_srt1);
    cudaGetSymbolAddress((void**)&off2, g_off2);
    cudaGetSymbolAddress((void**)&srt2, g_srt2);

    cudaFuncSetAttribute((void*)gemm_hmma_k<128, 256, 4, 4, false, false>,
                         cudaFuncAttributeMaxDynamicSharedMemorySize, SMEM_L1);
    cudaFuncSetAttribute((void*)gemm_hmma_k<64, 128, 2, 4, true, true>,
                         cudaFuncAttributeMaxDynamicSharedMemorySize, SMEM_L2);

    wsplit_all_k<<<(D * D + DOUT * D + 255) / 256, 256>>>(W1, w1hi, w1lo, W2, w2hi, w2lo);  // 0
    cudaMemsetAsync(cnt, 0, (N1_DST + N2_DST) * sizeof(int));
    hist_all_k<<<(E1 + E2 + 255) / 256, 256>>>(ed1, ed2, cnt);                              // 2
    scan_all_k<<<2, 1024>>>(cnt, cur, off1, off2);                                          // 3
    scatter_all_k<<<(E1 + E2 + 255) / 256, 256>>>(es1, ed1, es2, ed2, cur, srt1, srt2);     // 4

    // ---- layer 1 ----
    agg_split_k<false><<<N1_DST, 128>>>(feats, off1, srt1, a1h, nullptr);                   // 5
    {
        dim3 grid(D / 256, N1_DST / 128);   // (2, 352)
        gemm_hmma_k<128, 256, 4, 4, false, false><<<grid, 512, SMEM_L1>>>(
            a1h, nullptr, w1hi, nullptr, b1, h1, D, 1);                                     // 6
    }

    // ---- layer 2 ----
    agg_split_k<true><<<N2_DST, 128>>>(h1, off2, srt2, a2hi, a2lo);                         // 7
    {
        dim3 grid(DOUT / 128, N2_DST / 64);  // (2, 64)
        gemm_hmma_k<64, 128, 2, 4, true, true><<<grid, 256, SMEM_L2>>>(
            a2hi, a2lo, w2hi, w2lo, b2, out, DOUT, 0);                                      // 8
    }
}